// round 16
// baseline (speedup 1.0000x reference)
#include <cuda_runtime.h>
#include <cstdint>

// Problem constants (fixed by the dataset: emb [8,8,1024,1024] f32, gt_seg [8,1024,1024] i32)
#define B_      8
#define D_      8
#define HW_     (1024 * 1024)
#define C_      5
#define THREADS_ 256
#define NWARPS_ (THREADS_ / 32)
#define TOTAL_CTAS_ 148           // one CTA per SM, one full wave
#define NVALS_  50
#define NPAIRS_ (C_ * (C_ - 1))   // 20 ordered pairs
#define NRECS_  (2 * TOTAL_CTAS_) // each CTA emits <=2 batch-tagged partial records

// ---- TMA-bulk SMEM pipeline geometry ----
#define PXS_        1024                       // pixels per stage (4 per thread)
#define SPB_        (HW_ / PXS_)               // 1024 stages per batch
#define NST_        (SPB_ * B_)                // 8192 global stages
#define SEG_BYTES_  (PXS_ * 4)                 // 4 KB
#define ROW_BYTES_  (PXS_ * 4)                 // 4 KB per dim
#define STAGE_BYTES_ (SEG_BYTES_ + D_ * ROW_BYTES_)  // 36 KB
#define NS_         5                          // ring depth (185 KB < 227 KB opt-in cap)
#define MBAR_OFF_   0
#define DATA_OFF_   1024
#define SMEM_DYN_   (DATA_OFF_ + NS_ * STAGE_BYTES_)  // 185344 B

// NVALS layout per record:
//   [0..31]  S[c][d] c<4 | [32..39] T[d] | [40..43] q_c c<4 | [44] qT | [45..48] cnt_c c<4 | [49] n

typedef unsigned long long u64;

__device__ float g_partials[NRECS_][NVALS_];
__device__ int   g_pbat[NRECS_];  // batch tag per record (written every launch)
__device__ unsigned int g_done;   // zero at load; last block resets to 0 each launch

// ---- packed f32x2 helpers ----
__device__ __forceinline__ u64 pk2(float lo, float hi) {
    u64 r; asm("mov.b64 %0, {%1, %2};" : "=l"(r) : "f"(lo), "f"(hi)); return r;
}
__device__ __forceinline__ float2 upk2(u64 v) {
    float2 f; asm("mov.b64 {%0, %1}, %2;" : "=f"(f.x), "=f"(f.y) : "l"(v)); return f;
}
__device__ __forceinline__ void fma2(u64& a, u64 m, u64 v) {
    asm("fma.rn.f32x2 %0, %1, %2, %0;" : "+l"(a) : "l"(m), "l"(v));
}
__device__ __forceinline__ void add2(u64& a, u64 v) {
    asm("add.rn.f32x2 %0, %0, %1;" : "+l"(a) : "l"(v));
}

// ---- smem / mbarrier / bulk-copy helpers ----
__device__ __forceinline__ uint32_t smem_u32(const void* p) {
    uint32_t a; asm("{ .reg .u64 t; cvta.to.shared.u64 t, %1; cvt.u32.u64 %0, t; }" : "=r"(a) : "l"(p));
    return a;
}
__device__ __forceinline__ void mbar_init(uint32_t a, uint32_t cnt) {
    asm volatile("mbarrier.init.shared.b64 [%0], %1;" :: "r"(a), "r"(cnt) : "memory");
}
__device__ __forceinline__ void mbar_expect_tx(uint32_t a, uint32_t bytes) {
    asm volatile("mbarrier.arrive.expect_tx.shared.b64 _, [%0], %1;" :: "r"(a), "r"(bytes) : "memory");
}
__device__ __forceinline__ void mbar_arrive(uint32_t a) {
    asm volatile("mbarrier.arrive.shared.b64 _, [%0];" :: "r"(a) : "memory");
}
__device__ __forceinline__ void mbar_wait_acq(uint32_t a, uint32_t ph) {
    asm volatile(
        "{\n\t.reg .pred P;\n\t"
        "WL_%=:\n\t"
        "mbarrier.try_wait.parity.acquire.cta.shared::cta.b64 P, [%0], %1, 0x989680;\n\t"
        "@P bra.uni WD_%=;\n\t"
        "bra.uni WL_%=;\n\t"
        "WD_%=:\n\t}"
        :: "r"(a), "r"(ph) : "memory");
}
__device__ __forceinline__ void mbar_wait_rlx(uint32_t a, uint32_t ph) {
    asm volatile(
        "{\n\t.reg .pred P;\n\t"
        "WL_%=:\n\t"
        "mbarrier.try_wait.parity.relaxed.cta.shared::cta.b64 P, [%0], %1, 0x989680;\n\t"
        "@P bra.uni WD_%=;\n\t"
        "bra.uni WL_%=;\n\t"
        "WD_%=:\n\t}"
        :: "r"(a), "r"(ph) : "memory");
}
// Default L2 policy — R14 showed evict_first badly hurts saturated streaming reads.
__device__ __forceinline__ void bulk_g2s(uint32_t dst, const void* src, uint32_t bytes, uint32_t mbar) {
    asm volatile("cp.async.bulk.shared::cta.global.mbarrier::complete_tx::bytes [%0], [%1], %2, [%3];"
                 :: "r"(dst), "l"(src), "r"(bytes), "r"(mbar) : "memory");
}

// Issue one global stage st (batch = st>>10, local chunk = st&1023) into ring slot.
__device__ __forceinline__ void issue_stage(uint32_t sb, int slot, int st,
                                            const char* seg0, const char* emb0) {
    const uint32_t full = sb + MBAR_OFF_ + slot * 16;
    const uint32_t dst  = sb + DATA_OFF_ + slot * STAGE_BYTES_;
    const int bb    = st >> 10;
    const int local = st & (SPB_ - 1);
    const char* seg_g = seg0 + ((size_t)bb * HW_ + (size_t)local * PXS_) * 4;
    const char* emb_g = emb0 + ((size_t)bb * D_ * HW_ + (size_t)local * PXS_) * 4;
    mbar_expect_tx(full, STAGE_BYTES_);
    bulk_g2s(dst, seg_g, SEG_BYTES_, full);
#pragma unroll
    for (int d = 0; d < D_; d++)
        bulk_g2s(dst + SEG_BYTES_ + d * ROW_BYTES_, emb_g + (size_t)d * HW_ * 4, ROW_BYTES_, full);
}

__global__ void __launch_bounds__(THREADS_, 1)
lane_loss_fused_kernel(const float* __restrict__ emb, const int* __restrict__ seg,
                       float* __restrict__ out) {
    extern __shared__ char smem[];
    const uint32_t sb = smem_u32(smem);
    const int cj  = blockIdx.x;
    const int tid = threadIdx.x;
    const int lane = tid & 31;
    const int warp = tid >> 5;

    const char* seg0 = (const char*)seg;
    const char* emb0 = (const char*)emb;

    __shared__ float red[NWARPS_][NVALS_];

    if (tid == 0) {
#pragma unroll
        for (int s = 0; s < NS_; s++) {
            mbar_init(sb + MBAR_OFF_ + s * 16, 1);           // full: 1 expect_tx arrive + tx bytes
            mbar_init(sb + MBAR_OFF_ + s * 16 + 8, NWARPS_); // empty: one elected arrive per warp
        }
    }
    __syncthreads();

    // Contiguous balanced chunk of global stages: [start, end), size 55 or 56.
    const int start = (cj * NST_) / TOTAL_CTAS_;
    const int end   = ((cj + 1) * NST_) / TOTAL_CTAS_;
    const int n     = end - start;
    const int b0    = start >> 10;
    const int blast = (end - 1) >> 10;
    const int crossed  = (b0 != blast) ? 1 : 0;
    const int st_bound = (b0 + 1) << 10;     // first stage of the next batch (if crossed)

    // Producer prologue: fill the ring
    if (tid == 0) {
#pragma unroll
        for (int k = 0; k < NS_; k++)
            issue_stage(sb, k, start + k, seg0, emb0);
    }

    // ---------------- Pass 1: pipelined streaming reduction ----------------
    u64 accS[4][D_], accT[D_], accQ[4], accQT, accC[4];
#pragma unroll
    for (int c = 0; c < 4; c++) { accQ[c] = 0ull; accC[c] = 0ull;
#pragma unroll
        for (int d = 0; d < D_; d++) accS[c][d] = 0ull; }
#pragma unroll
    for (int d = 0; d < D_; d++) accT[d] = 0ull;
    accQT = 0ull;
    int n_seg = 0;   // iterations in current segment

    // Flush current accumulators as record `recidx` tagged with batch `bbval`, then reset.
#define FLUSH_SEG(recidx, bbval) do {                                                   \
        float vals[NVALS_];                                                             \
        _Pragma("unroll")                                                               \
        for (int c = 0; c < 4; c++)                                                     \
            _Pragma("unroll")                                                           \
            for (int d = 0; d < D_; d++) { float2 f = upk2(accS[c][d]); vals[c*D_+d] = f.x + f.y; } \
        _Pragma("unroll")                                                               \
        for (int d = 0; d < D_; d++) { float2 f = upk2(accT[d]); vals[32+d] = f.x + f.y; } \
        _Pragma("unroll")                                                               \
        for (int c = 0; c < 4; c++) { float2 f = upk2(accQ[c]); vals[40+c] = f.x + f.y; } \
        { float2 f = upk2(accQT); vals[44] = f.x + f.y; }                               \
        _Pragma("unroll")                                                               \
        for (int c = 0; c < 4; c++) { float2 f = upk2(accC[c]); vals[45+c] = f.x + f.y; } \
        vals[49] = (float)(n_seg * 4);                                                  \
        _Pragma("unroll")                                                               \
        for (int kk = 0; kk < NVALS_; kk++)                                             \
            _Pragma("unroll")                                                           \
            for (int off = 16; off > 0; off >>= 1)                                      \
                vals[kk] += __shfl_xor_sync(0xffffffffu, vals[kk], off);                \
        if (lane == 0)                                                                  \
            _Pragma("unroll")                                                           \
            for (int kk = 0; kk < NVALS_; kk++) red[warp][kk] = vals[kk];               \
        __syncthreads();                                                                \
        if (tid < NVALS_) {                                                             \
            float s_ = 0.f;                                                             \
            _Pragma("unroll")                                                           \
            for (int w = 0; w < NWARPS_; w++) s_ += red[w][tid];                        \
            g_partials[recidx][tid] = s_;                                               \
        }                                                                               \
        if (tid == 0) g_pbat[recidx] = (bbval);                                         \
        __syncthreads();                                                                \
        _Pragma("unroll")                                                               \
        for (int c = 0; c < 4; c++) { accQ[c] = 0ull; accC[c] = 0ull;                   \
            _Pragma("unroll")                                                           \
            for (int d = 0; d < D_; d++) accS[c][d] = 0ull; }                           \
        _Pragma("unroll")                                                               \
        for (int d = 0; d < D_; d++) accT[d] = 0ull;                                    \
        accQT = 0ull; n_seg = 0;                                                        \
    } while (0)

    int slot = 0, ph = 0;            // shared cursor: refill slot == consume slot

    for (int k = 0; k < n; k++) {
        const int st = start + k;
        if (crossed && st == st_bound)
            FLUSH_SEG(2 * cj, b0);   // close segment 1 (batch b0)

        const uint32_t full  = sb + MBAR_OFF_ + slot * 16;
        const uint32_t empty = full + 8;
        mbar_wait_acq(full, ph);

        // (a) Drain the stage into registers first (144 B/thread)
        const char* base = smem + DATA_OFF_ + slot * STAGE_BYTES_;
        const int4 s4 = *(const int4*)(base + tid * 16);
        float4 v[D_];
#pragma unroll
        for (int d = 0; d < D_; d++)
            v[d] = *(const float4*)(base + SEG_BYTES_ + d * ROW_BYTES_ + tid * 16);

        // (b) Release the slot immediately — one elected arrive per warp
        __syncwarp();
        if (lane == 0) mbar_arrive(empty);

        // (c) Refill this slot right away (gated on loads, not compute)
        if (tid == 0 && k + NS_ < n) {
            mbar_wait_rlx(empty, ph);
            issue_stage(sb, slot, start + k + NS_, seg0, emb0);
        }

        // (d) Compute from registers
        n_seg++;
        u64 m01[4], m23[4];
#pragma unroll
        for (int c = 0; c < 4; c++) {
            m01[c] = pk2(s4.x == c ? 1.f : 0.f, s4.y == c ? 1.f : 0.f);
            m23[c] = pk2(s4.z == c ? 1.f : 0.f, s4.w == c ? 1.f : 0.f);
        }

        u64 q01 = 0ull, q23 = 0ull;
#pragma unroll
        for (int d = 0; d < D_; d++) {
            const u64 v01 = pk2(v[d].x, v[d].y);
            const u64 v23 = pk2(v[d].z, v[d].w);
            fma2(q01, v01, v01);
            fma2(q23, v23, v23);
            add2(accT[d], v01);
            add2(accT[d], v23);
#pragma unroll
            for (int c = 0; c < 4; c++) {
                fma2(accS[c][d], m01[c], v01);
                fma2(accS[c][d], m23[c], v23);
            }
        }
#pragma unroll
        for (int c = 0; c < 4; c++) {
            fma2(accQ[c], m01[c], q01);
            fma2(accQ[c], m23[c], q23);
            add2(accC[c], m01[c]);
            add2(accC[c], m23[c]);
        }
        add2(accQT, q01);
        add2(accQT, q23);

        if (++slot == NS_) { slot = 0; ph ^= 1; }
    }

    // Final segment flush (batch blast); record index 2*cj + crossed.
    FLUSH_SEG(2 * cj + crossed, blast);

    // If no crossing, emit a zero record so every launch writes both slots (graph-replay safe).
    if (!crossed) {
        if (tid < NVALS_) g_partials[2 * cj + 1][tid] = 0.f;
        if (tid == 0)     g_pbat[2 * cj + 1] = 0;     // zeros into batch 0: harmless, deterministic
    }

    // ---------------- Last-block-done handoff ----------------
    __shared__ unsigned int amLast;
    __threadfence();
    if (tid == 0) {
        unsigned int vv = atomicAdd(&g_done, 1u);
        amLast = (vv == TOTAL_CTAS_ - 1) ? 1u : 0u;
    }
    __syncthreads();
    if (!amLast) return;
    __threadfence();
    if (tid == 0) g_done = 0;

    // ---------------- Pass 2: finalize (fp32, deterministic) ----------------
    __shared__ float sv[B_][NVALS_];
    __shared__ float mean_s[B_][C_][D_];
    __shared__ float sum_s[B_][C_][D_];
    __shared__ float var_s[B_][C_];
    __shared__ float hinge_s[B_][NPAIRS_];
    const int t = tid;

    // Stage 1: fold 296 batch-tagged records, fixed order -> deterministic.
    if (t < NVALS_) {
        float acc0 = 0.f, acc1 = 0.f, acc2 = 0.f, acc3 = 0.f;
        float acc4 = 0.f, acc5 = 0.f, acc6 = 0.f, acc7 = 0.f;
        for (int rec = 0; rec < NRECS_; rec++) {
            const float vv = g_partials[rec][t];
            const int  bb = g_pbat[rec];
            acc0 += (bb == 0) ? vv : 0.f;
            acc1 += (bb == 1) ? vv : 0.f;
            acc2 += (bb == 2) ? vv : 0.f;
            acc3 += (bb == 3) ? vv : 0.f;
            acc4 += (bb == 4) ? vv : 0.f;
            acc5 += (bb == 5) ? vv : 0.f;
            acc6 += (bb == 6) ? vv : 0.f;
            acc7 += (bb == 7) ? vv : 0.f;
        }
        sv[0][t] = acc0; sv[1][t] = acc1; sv[2][t] = acc2; sv[3][t] = acc3;
        sv[4][t] = acc4; sv[5][t] = acc5; sv[6][t] = acc6; sv[7][t] = acc7;
    }
    __syncthreads();

    for (int idx = t; idx < B_ * C_ * D_; idx += THREADS_) {
        const int bb = idx / (C_ * D_);
        const int c  = (idx / D_) % C_;
        const int d  = idx % D_;
        float sm, cn;
        if (c < 4) { sm = sv[bb][c * D_ + d]; cn = sv[bb][45 + c]; }
        else {
            sm = sv[bb][32 + d] - (sv[bb][0 * D_ + d] + sv[bb][1 * D_ + d] +
                                   sv[bb][2 * D_ + d] + sv[bb][3 * D_ + d]);
            cn = sv[bb][49] - (sv[bb][45] + sv[bb][46] + sv[bb][47] + sv[bb][48]);
        }
        sum_s[bb][c][d]  = sm;
        mean_s[bb][c][d] = sm / cn;
    }
    __syncthreads();

    for (int idx = t; idx < B_ * C_; idx += THREADS_) {
        const int bb = idx / C_, c = idx % C_;
        float q;
        if (c < 4) q = sv[bb][40 + c];
        else       q = sv[bb][44] - (sv[bb][40] + sv[bb][41] + sv[bb][42] + sv[bb][43]);
        float m2 = 0.f;
#pragma unroll
        for (int d = 0; d < D_; d++) m2 += sum_s[bb][c][d] * mean_s[bb][c][d];
        float ssv = q - m2;
        if (ssv < 0.f) ssv = 0.f;
        const float r = sqrtf(ssv) - 0.5f;           // SIGMA_V
        var_s[bb][c] = r > 0.f ? r : 0.f;
    }

    for (int idx = t; idx < B_ * NPAIRS_; idx += THREADS_) {
        const int bb = idx / NPAIRS_, p = idx % NPAIRS_;
        const int i = p / (C_ - 1);
        int j = p % (C_ - 1);
        if (j >= i) j++;
        float d2 = 0.f;
#pragma unroll
        for (int d = 0; d < D_; d++) {
            const float df = mean_s[bb][i][d] - mean_s[bb][j][d];
            d2 += df * df;
        }
        const float h = 3.0f - sqrtf(d2);            // SIGMA_D
        hinge_s[bb][p] = h > 0.f ? h : 0.f;
    }
    __syncthreads();

    if (t == 0) {
        float total = 0.f;
        for (int bb = 0; bb < B_; bb++) {
            float vvv = 0.f;
#pragma unroll
            for (int c = 0; c < C_; c++) vvv += var_s[bb][c];
            float dl = 0.f;
#pragma unroll
            for (int p = 0; p < NPAIRS_; p++) dl += hinge_s[bb][p];
            total += vvv / (float)C_ + dl / (float)NPAIRS_;
        }
        out[0] = total / (float)B_;
    }
}

extern "C" void kernel_launch(void* const* d_in, const int* in_sizes, int n_in,
                              void* d_out, int out_size) {
    const float* emb = (const float*)d_in[0];   // [8, 8, 1024, 1024] f32
    const int*   seg = (const int*)d_in[1];     // [8, 1024, 1024] i32
    (void)in_sizes; (void)n_in; (void)out_size;

    cudaFuncSetAttribute(lane_loss_fused_kernel,
                         cudaFuncAttributeMaxDynamicSharedMemorySize, SMEM_DYN_);
    lane_loss_fused_kernel<<<TOTAL_CTAS_, THREADS_, SMEM_DYN_>>>(emb, seg, (float*)d_out);
}

// round 17
// speedup vs baseline: 1.3624x; 1.3624x over previous
#include <cuda_runtime.h>
#include <cstdint>

// Problem constants (fixed by the dataset: emb [8,8,1024,1024] f32, gt_seg [8,1024,1024] i32)
#define B_      8
#define D_      8
#define HW_     (1024 * 1024)
#define C_      5
#define THREADS_ 256
#define NWARPS_ (THREADS_ / 32)
#define GROUPS_  4                // CTA groups; group g owns batches {2g, 2g+1}
#define GCTAS_   37               // CTAs per group
#define TOTAL_CTAS_ (GROUPS_ * GCTAS_)   // 148 = one CTA per SM, one wave
#define NVALS_  50
#define NPAIRS_ (C_ * (C_ - 1))   // 20 ordered pairs
#define NRECS_  (2 * TOTAL_CTAS_) // exactly 2 batch-known records per CTA

// ---- TMA-bulk SMEM pipeline geometry ----
#define PXS_        1024                       // pixels per stage (4 per thread)
#define SPB_        (HW_ / PXS_)               // 1024 stages per batch
#define SPG_        (2 * SPB_)                 // 2048 stages per group (2 batches)
#define SEG_BYTES_  (PXS_ * 4)                 // 4 KB
#define ROW_BYTES_  (PXS_ * 4)                 // 4 KB per dim
#define STAGE_BYTES_ (SEG_BYTES_ + D_ * ROW_BYTES_)  // 36 KB
#define NS_         5                          // ring depth (185 KB < 227 KB opt-in cap)
#define MBAR_OFF_   0
#define DATA_OFF_   1024
#define SMEM_DYN_   (DATA_OFF_ + NS_ * STAGE_BYTES_)  // 185344 B

// NVALS layout per record:
//   [0..31]  S[c][d] c<4 | [32..39] T[d] | [40..43] q_c c<4 | [44] qT | [45..48] cnt_c c<4 | [49] n

typedef unsigned long long u64;

__device__ float g_partials[NRECS_][NVALS_];
__device__ unsigned int g_done;   // zero at load; last block resets to 0 each launch

// ---- packed f32x2 helpers ----
__device__ __forceinline__ u64 pk2(float lo, float hi) {
    u64 r; asm("mov.b64 %0, {%1, %2};" : "=l"(r) : "f"(lo), "f"(hi)); return r;
}
__device__ __forceinline__ float2 upk2(u64 v) {
    float2 f; asm("mov.b64 {%0, %1}, %2;" : "=f"(f.x), "=f"(f.y) : "l"(v)); return f;
}
__device__ __forceinline__ void fma2(u64& a, u64 m, u64 v) {
    asm("fma.rn.f32x2 %0, %1, %2, %0;" : "+l"(a) : "l"(m), "l"(v));
}
__device__ __forceinline__ void add2(u64& a, u64 v) {
    asm("add.rn.f32x2 %0, %0, %1;" : "+l"(a) : "l"(v));
}

// ---- smem / mbarrier / bulk-copy helpers ----
__device__ __forceinline__ uint32_t smem_u32(const void* p) {
    uint32_t a; asm("{ .reg .u64 t; cvta.to.shared.u64 t, %1; cvt.u32.u64 %0, t; }" : "=r"(a) : "l"(p));
    return a;
}
__device__ __forceinline__ void mbar_init(uint32_t a, uint32_t cnt) {
    asm volatile("mbarrier.init.shared.b64 [%0], %1;" :: "r"(a), "r"(cnt) : "memory");
}
__device__ __forceinline__ void mbar_expect_tx(uint32_t a, uint32_t bytes) {
    asm volatile("mbarrier.arrive.expect_tx.shared.b64 _, [%0], %1;" :: "r"(a), "r"(bytes) : "memory");
}
__device__ __forceinline__ void mbar_arrive(uint32_t a) {
    asm volatile("mbarrier.arrive.shared.b64 _, [%0];" :: "r"(a) : "memory");
}
__device__ __forceinline__ void mbar_wait_acq(uint32_t a, uint32_t ph) {
    asm volatile(
        "{\n\t.reg .pred P;\n\t"
        "WL_%=:\n\t"
        "mbarrier.try_wait.parity.acquire.cta.shared::cta.b64 P, [%0], %1, 0x989680;\n\t"
        "@P bra.uni WD_%=;\n\t"
        "bra.uni WL_%=;\n\t"
        "WD_%=:\n\t}"
        :: "r"(a), "r"(ph) : "memory");
}
__device__ __forceinline__ void mbar_wait_rlx(uint32_t a, uint32_t ph) {
    asm volatile(
        "{\n\t.reg .pred P;\n\t"
        "WL_%=:\n\t"
        "mbarrier.try_wait.parity.relaxed.cta.shared::cta.b64 P, [%0], %1, 0x989680;\n\t"
        "@P bra.uni WD_%=;\n\t"
        "bra.uni WL_%=;\n\t"
        "WD_%=:\n\t}"
        :: "r"(a), "r"(ph) : "memory");
}
// Default L2 policy — R14 showed evict_first badly hurts saturated streaming reads.
__device__ __forceinline__ void bulk_g2s(uint32_t dst, const void* src, uint32_t bytes, uint32_t mbar) {
    asm volatile("cp.async.bulk.shared::cta.global.mbarrier::complete_tx::bytes [%0], [%1], %2, [%3];"
                 :: "r"(dst), "l"(src), "r"(bytes), "r"(mbar) : "memory");
}

// Issue one global stage st (batch = st>>10, local = st&1023) into ring slot.
__device__ __forceinline__ void issue_stage(uint32_t sb, int slot, int st,
                                            const char* seg0, const char* emb0) {
    const uint32_t full = sb + MBAR_OFF_ + slot * 16;
    const uint32_t dst  = sb + DATA_OFF_ + slot * STAGE_BYTES_;
    const int bb    = st >> 10;
    const int local = st & (SPB_ - 1);
    const char* seg_g = seg0 + ((size_t)bb * HW_ + (size_t)local * PXS_) * 4;
    const char* emb_g = emb0 + ((size_t)bb * D_ * HW_ + (size_t)local * PXS_) * 4;
    mbar_expect_tx(full, STAGE_BYTES_);
    bulk_g2s(dst, seg_g, SEG_BYTES_, full);
#pragma unroll
    for (int d = 0; d < D_; d++)
        bulk_g2s(dst + SEG_BYTES_ + d * ROW_BYTES_, emb_g + (size_t)d * HW_ * 4, ROW_BYTES_, full);
}

__global__ void __launch_bounds__(THREADS_, 1)
lane_loss_fused_kernel(const float* __restrict__ emb, const int* __restrict__ seg,
                       float* __restrict__ out) {
    extern __shared__ char smem[];
    const uint32_t sb = smem_u32(smem);
    const int cj  = blockIdx.x;
    const int g   = cj / GCTAS_;      // group -> batches {2g, 2g+1}
    const int cg  = cj % GCTAS_;      // lane within group
    const int tid = threadIdx.x;
    const int lane = tid & 31;
    const int warp = tid >> 5;

    const char* seg0 = (const char*)seg;
    const char* emb0 = (const char*)emb;

    __shared__ float red[NWARPS_][NVALS_];

    if (tid == 0) {
#pragma unroll
        for (int s = 0; s < NS_; s++) {
            mbar_init(sb + MBAR_OFF_ + s * 16, 1);           // full: 1 expect_tx arrive + tx bytes
            mbar_init(sb + MBAR_OFF_ + s * 16 + 8, NWARPS_); // empty: one elected arrive per warp
        }
    }
    __syncthreads();

    // Interleaved stages within the group: st(k) = 2048*g + cg + k*37, k=0..nmine-1.
    // Adjacent CTAs read adjacent stages at the same time -> dense 37-wide fronts.
    const int base_st = g * SPG_;
    const int nmine   = (SPG_ - cg + GCTAS_ - 1) / GCTAS_;        // 56 (cg<13) or 55
    const int k_cross = (SPB_ - cg + GCTAS_ - 1) / GCTAS_;        // first k in batch 2g+1

    // Producer prologue: fill the ring
    if (tid == 0) {
#pragma unroll
        for (int k = 0; k < NS_; k++)
            issue_stage(sb, k, base_st + cg + k * GCTAS_, seg0, emb0);
    }

    // ---------------- Pass 1: pipelined streaming reduction ----------------
    u64 accS[4][D_], accT[D_], accQ[4], accQT, accC[4];
#pragma unroll
    for (int c = 0; c < 4; c++) { accQ[c] = 0ull; accC[c] = 0ull;
#pragma unroll
        for (int d = 0; d < D_; d++) accS[c][d] = 0ull; }
#pragma unroll
    for (int d = 0; d < D_; d++) accT[d] = 0ull;
    accQT = 0ull;
    int n_seg = 0;   // iterations in current segment

    // Flush current accumulators as record `recidx`, then reset. Uniform across block.
#define FLUSH_SEG(recidx) do {                                                          \
        float vals[NVALS_];                                                             \
        _Pragma("unroll")                                                               \
        for (int c = 0; c < 4; c++)                                                     \
            _Pragma("unroll")                                                           \
            for (int d = 0; d < D_; d++) { float2 f = upk2(accS[c][d]); vals[c*D_+d] = f.x + f.y; } \
        _Pragma("unroll")                                                               \
        for (int d = 0; d < D_; d++) { float2 f = upk2(accT[d]); vals[32+d] = f.x + f.y; } \
        _Pragma("unroll")                                                               \
        for (int c = 0; c < 4; c++) { float2 f = upk2(accQ[c]); vals[40+c] = f.x + f.y; } \
        { float2 f = upk2(accQT); vals[44] = f.x + f.y; }                               \
        _Pragma("unroll")                                                               \
        for (int c = 0; c < 4; c++) { float2 f = upk2(accC[c]); vals[45+c] = f.x + f.y; } \
        vals[49] = (float)(n_seg * 4);                                                  \
        _Pragma("unroll")                                                               \
        for (int kk = 0; kk < NVALS_; kk++)                                             \
            _Pragma("unroll")                                                           \
            for (int off = 16; off > 0; off >>= 1)                                      \
                vals[kk] += __shfl_xor_sync(0xffffffffu, vals[kk], off);                \
        if (lane == 0)                                                                  \
            _Pragma("unroll")                                                           \
            for (int kk = 0; kk < NVALS_; kk++) red[warp][kk] = vals[kk];               \
        __syncthreads();                                                                \
        if (tid < NVALS_) {                                                             \
            float s_ = 0.f;                                                             \
            _Pragma("unroll")                                                           \
            for (int w = 0; w < NWARPS_; w++) s_ += red[w][tid];                        \
            g_partials[recidx][tid] = s_;                                               \
        }                                                                               \
        __syncthreads();                                                                \
        _Pragma("unroll")                                                               \
        for (int c = 0; c < 4; c++) { accQ[c] = 0ull; accC[c] = 0ull;                   \
            _Pragma("unroll")                                                           \
            for (int d = 0; d < D_; d++) accS[c][d] = 0ull; }                           \
        _Pragma("unroll")                                                               \
        for (int d = 0; d < D_; d++) accT[d] = 0ull;                                    \
        accQT = 0ull; n_seg = 0;                                                        \
    } while (0)

    int slot = 0, ph = 0;            // shared cursor: refill slot == consume slot

    for (int k = 0; k < nmine; k++) {
        if (k == k_cross)
            FLUSH_SEG(2 * cj);       // close batch-2g segment (every CTA crosses exactly once)

        const uint32_t full  = sb + MBAR_OFF_ + slot * 16;
        const uint32_t empty = full + 8;
        mbar_wait_acq(full, ph);

        // (a) Drain the stage into registers first (144 B/thread)
        const char* base = smem + DATA_OFF_ + slot * STAGE_BYTES_;
        const int4 s4 = *(const int4*)(base + tid * 16);
        float4 v[D_];
#pragma unroll
        for (int d = 0; d < D_; d++)
            v[d] = *(const float4*)(base + SEG_BYTES_ + d * ROW_BYTES_ + tid * 16);

        // (b) Release the slot immediately — one elected arrive per warp
        __syncwarp();
        if (lane == 0) mbar_arrive(empty);

        // (c) Refill this slot right away (gated on loads, not compute)
        if (tid == 0 && k + NS_ < nmine) {
            mbar_wait_rlx(empty, ph);
            issue_stage(sb, slot, base_st + cg + (k + NS_) * GCTAS_, seg0, emb0);
        }

        // (d) Compute from registers
        n_seg++;
        u64 m01[4], m23[4];
#pragma unroll
        for (int c = 0; c < 4; c++) {
            m01[c] = pk2(s4.x == c ? 1.f : 0.f, s4.y == c ? 1.f : 0.f);
            m23[c] = pk2(s4.z == c ? 1.f : 0.f, s4.w == c ? 1.f : 0.f);
        }

        u64 q01 = 0ull, q23 = 0ull;
#pragma unroll
        for (int d = 0; d < D_; d++) {
            const u64 v01 = pk2(v[d].x, v[d].y);
            const u64 v23 = pk2(v[d].z, v[d].w);
            fma2(q01, v01, v01);
            fma2(q23, v23, v23);
            add2(accT[d], v01);
            add2(accT[d], v23);
#pragma unroll
            for (int c = 0; c < 4; c++) {
                fma2(accS[c][d], m01[c], v01);
                fma2(accS[c][d], m23[c], v23);
            }
        }
#pragma unroll
        for (int c = 0; c < 4; c++) {
            fma2(accQ[c], m01[c], q01);
            fma2(accQ[c], m23[c], q23);
            add2(accC[c], m01[c]);
            add2(accC[c], m23[c]);
        }
        add2(accQT, q01);
        add2(accQT, q23);

        if (++slot == NS_) { slot = 0; ph ^= 1; }
    }

    // Final segment flush (batch 2g+1).
    FLUSH_SEG(2 * cj + 1);

    // ---------------- Last-block-done handoff ----------------
    __shared__ unsigned int amLast;
    __threadfence();
    if (tid == 0) {
        unsigned int vv = atomicAdd(&g_done, 1u);
        amLast = (vv == TOTAL_CTAS_ - 1) ? 1u : 0u;
    }
    __syncthreads();
    if (!amLast) return;
    __threadfence();
    if (tid == 0) g_done = 0;

    // ---------------- Pass 2: finalize (fp32, deterministic) ----------------
    __shared__ float sv[B_][NVALS_];
    __shared__ float mean_s[B_][C_][D_];
    __shared__ float sum_s[B_][C_][D_];
    __shared__ float var_s[B_][C_];
    __shared__ float hinge_s[B_][NPAIRS_];
    const int t = tid;

    // Stage 1: fold records. Batch bb's records are statically known:
    // rec = 2*(GCTAS_*(bb/2) + cg) + (bb&1), cg = 0..36. Fixed order -> deterministic.
    if (t < NVALS_) {
#pragma unroll
        for (int bb = 0; bb < B_; bb++) {
            const int gg = bb >> 1, par = bb & 1;
            float s = 0.f;
            for (int c2 = 0; c2 < GCTAS_; c2++)
                s += g_partials[2 * (GCTAS_ * gg + c2) + par][t];
            sv[bb][t] = s;
        }
    }
    __syncthreads();

    for (int idx = t; idx < B_ * C_ * D_; idx += THREADS_) {
        const int bb = idx / (C_ * D_);
        const int c  = (idx / D_) % C_;
        const int d  = idx % D_;
        float sm, cn;
        if (c < 4) { sm = sv[bb][c * D_ + d]; cn = sv[bb][45 + c]; }
        else {
            sm = sv[bb][32 + d] - (sv[bb][0 * D_ + d] + sv[bb][1 * D_ + d] +
                                   sv[bb][2 * D_ + d] + sv[bb][3 * D_ + d]);
            cn = sv[bb][49] - (sv[bb][45] + sv[bb][46] + sv[bb][47] + sv[bb][48]);
        }
        sum_s[bb][c][d]  = sm;
        mean_s[bb][c][d] = sm / cn;
    }
    __syncthreads();

    for (int idx = t; idx < B_ * C_; idx += THREADS_) {
        const int bb = idx / C_, c = idx % C_;
        float q;
        if (c < 4) q = sv[bb][40 + c];
        else       q = sv[bb][44] - (sv[bb][40] + sv[bb][41] + sv[bb][42] + sv[bb][43]);
        float m2 = 0.f;
#pragma unroll
        for (int d = 0; d < D_; d++) m2 += sum_s[bb][c][d] * mean_s[bb][c][d];
        float ssv = q - m2;
        if (ssv < 0.f) ssv = 0.f;
        const float r = sqrtf(ssv) - 0.5f;           // SIGMA_V
        var_s[bb][c] = r > 0.f ? r : 0.f;
    }

    for (int idx = t; idx < B_ * NPAIRS_; idx += THREADS_) {
        const int bb = idx / NPAIRS_, p = idx % NPAIRS_;
        const int i = p / (C_ - 1);
        int j = p % (C_ - 1);
        if (j >= i) j++;
        float d2 = 0.f;
#pragma unroll
        for (int d = 0; d < D_; d++) {
            const float df = mean_s[bb][i][d] - mean_s[bb][j][d];
            d2 += df * df;
        }
        const float h = 3.0f - sqrtf(d2);            // SIGMA_D
        hinge_s[bb][p] = h > 0.f ? h : 0.f;
    }
    __syncthreads();

    if (t == 0) {
        float total = 0.f;
        for (int bb = 0; bb < B_; bb++) {
            float vvv = 0.f;
#pragma unroll
            for (int c = 0; c < C_; c++) vvv += var_s[bb][c];
            float dl = 0.f;
#pragma unroll
            for (int p = 0; p < NPAIRS_; p++) dl += hinge_s[bb][p];
            total += vvv / (float)C_ + dl / (float)NPAIRS_;
        }
        out[0] = total / (float)B_;
    }
}

extern "C" void kernel_launch(void* const* d_in, const int* in_sizes, int n_in,
                              void* d_out, int out_size) {
    const float* emb = (const float*)d_in[0];   // [8, 8, 1024, 1024] f32
    const int*   seg = (const int*)d_in[1];     // [8, 1024, 1024] i32
    (void)in_sizes; (void)n_in; (void)out_size;

    cudaFuncSetAttribute(lane_loss_fused_kernel,
                         cudaFuncAttributeMaxDynamicSharedMemorySize, SMEM_DYN_);
    lane_loss_fused_kernel<<<TOTAL_CTAS_, THREADS_, SMEM_DYN_>>>(emb, seg, (float*)d_out);
}